// round 15
// baseline (speedup 1.0000x reference)
#include <cuda_runtime.h>
#include <cuda_fp16.h>
#include <cstdint>
#include <cstddef>

#define B 128
#define P 196
#define F 2048
#define H 512
#define NF 512
#define E 512
#define V 10000
#define L 20
#define T 19
#define NCOMBO 4608       // 512 (Wha) + 2048 (Wfb) + 2048 (Whh)
#define BN_SCALE 0.9999950000374997f   // 1/sqrt(1+1e-5)

typedef unsigned long long ull;

// ---------------- scratch (static device globals) ----------------
__device__ float g_feat[B * F];
__device__ float g_feat_att[(size_t)B * P * NF];       // 51.4 MB
__device__ float g_h0[B * H];
__device__ float g_Hall[(size_t)T * B * H];            // h_{t+1} for t=0..18 (5 MB)
__device__ float g_c[B * H];
__device__ float g_hWha[B * NF];
__device__ float g_e[B * P];
__device__ float g_gatepre[B * F];
__device__ float g_gatesH[B * 4 * H];
__device__ float g_xgc[B * F];
__device__ float g_bihh[4 * H];
__device__ float g_embseq[(size_t)T * B * E];
__device__ float g_embW[(size_t)T * B * 4 * H];        // 19.9 MB
__device__ float g_part[4 * 1024 * 1024];              // split-K partials (16 MB)
__device__ __half g_ench[(size_t)B * P * F];           // fp16 enc copy, 102.8 MB

// packed hi/lo f16 weight planes (pre-swizzled smem images, 32 KB per (nblk,chunk))
__device__ uint8_t g_pk_wcat4[(size_t)115 * 8 * 32768];   // [Wha|Wfb|Whh|Wfc] 30.1 MB
__device__ uint8_t g_pk_wihF[(size_t)16 * 32 * 32768];    // 16.8 MB
__device__ uint8_t g_pk_wihE[(size_t)16 * 8 * 32768];     // 4.2 MB
__device__ uint8_t g_pk_wfa[(size_t)4 * 32 * 32768];      // 4.2 MB
__device__ uint8_t g_pk_whc0[(size_t)8 * 32 * 32768];     // [Wh0|Wc0] 8.4 MB

__device__ __forceinline__ float sigmoidf(float x) { return 1.0f / (1.0f + expf(-x)); }

__device__ __forceinline__ uint32_t h2u(__half2 h) {
    uint32_t u;
    memcpy(&u, &h, 4);
    return u;
}

// ---------------- mma.sync helpers (non-'a' ISA) ----------------
__device__ __forceinline__ uint32_t smem_u32(const void* p) {
    uint32_t a;
    asm("{ .reg .u64 t; cvta.to.shared.u64 t, %1; cvt.u32.u64 %0, t; }" : "=r"(a) : "l"(p));
    return a;
}
__device__ __forceinline__ void ldsm4(uint32_t* r, uint32_t addr) {
    asm volatile("ldmatrix.sync.aligned.m8n8.x4.shared.b16 {%0,%1,%2,%3}, [%4];"
                 : "=r"(r[0]), "=r"(r[1]), "=r"(r[2]), "=r"(r[3]) : "r"(addr));
}
__device__ __forceinline__ void mma16816(float* c, const uint32_t* a, const uint32_t* b) {
    asm volatile(
        "mma.sync.aligned.m16n8k16.row.col.f32.f16.f16.f32 "
        "{%0,%1,%2,%3}, {%4,%5,%6,%7}, {%8,%9}, {%0,%1,%2,%3};"
        : "+f"(c[0]), "+f"(c[1]), "+f"(c[2]), "+f"(c[3])
        : "r"(a[0]), "r"(a[1]), "r"(a[2]), "r"(a[3]), "r"(b[0]), "r"(b[1]));
}
__device__ __forceinline__ uint32_t swz(uint32_t off) { return off ^ ((off >> 3) & 0x70); }
#define CP_ASYNC16(saddr, gaddr) \
    asm volatile("cp.async.cg.shared.global [%0], [%1], 16;" :: "r"(saddr), "l"(gaddr))

// split fp32 pair -> f16x2 hi word + f16x2 lo word
__device__ __forceinline__ void conv2h(float x, float y, uint32_t& hw, uint32_t& lw) {
    __half hx = __float2half_rn(x), hy = __float2half_rn(y);
    float rx = x - __half2float(hx);
    float ry = y - __half2float(hy);
    __half lx = __float2half_rn(rx), ly = __float2half_rn(ry);
    hw = ((uint32_t)__half_as_ushort(hy) << 16) | (uint32_t)__half_as_ushort(hx);
    lw = ((uint32_t)__half_as_ushort(ly) << 16) | (uint32_t)__half_as_ushort(lx);
}

// ---------------- weight pack kernel: fp32 (NxK,ldb) -> hi/lo planes, swizzled ------
__global__ void pack_kernel(const float* __restrict__ src, uint8_t* __restrict__ dst,
                            int N, int ldb) {
    int nblk = blockIdx.x, chunk = blockIdx.y, tid = threadIdx.x;
    int r = tid >> 1, c0 = (tid & 1) * 32;
    int row = nblk * 128 + r;
    bool ok = row < N;
    const float* s = src + (size_t)row * ldb + chunk * 64 + c0;
    uint8_t* base = dst + ((size_t)nblk * gridDim.y + chunk) * 32768;
#pragma unroll
    for (int g = 0; g < 4; g++) {
        float4 v0 = ok ? *(const float4*)(s + g * 8)     : make_float4(0.f, 0.f, 0.f, 0.f);
        float4 v1 = ok ? *(const float4*)(s + g * 8 + 4) : make_float4(0.f, 0.f, 0.f, 0.f);
        uint32_t h0, l0, h1, l1, h2, l2, h3, l3;
        conv2h(v0.x, v0.y, h0, l0); conv2h(v0.z, v0.w, h1, l1);
        conv2h(v1.x, v1.y, h2, l2); conv2h(v1.z, v1.w, h3, l3);
        uint32_t sw = swz((uint32_t)r * 128 + (uint32_t)(c0 + g * 8) * 2);
        *(uint4*)(base + sw)         = make_uint4(h0, h1, h2, h3);
        *(uint4*)(base + 16384 + sw) = make_uint4(l0, l1, l2, l3);
    }
}

// ---------------- epilogue param block ----------------
struct EpiP {
    int mode;            // 0 partial, 1 bias-direct, 2 combo-scatter (S==1 ONLY), 3 batched-preds
    const float* bias;   // mode 1
    const float* bha; const float* bfb; const float* bihh; const float* bfc;
    const int* lens;
    float* hWha; float* gatepre; float* gatesH; float* out_pred;
};

__device__ __forceinline__ void epi_store(const EpiP& ep, float* C, int M, int N, int z,
                                          int row, int col, float v) {
    if (col >= N) return;
    if (ep.mode == 0) {
        C[(size_t)z * M * N + (size_t)row * N + col] = v;
    } else if (ep.mode == 1) {
        C[(size_t)row * N + col] = ep.bias ? v + ep.bias[col] : v;
    } else if (ep.mode == 2) {
        if (col < 512)       ep.hWha[row * 512 + col] = v + ep.bha[col];
        else if (col < 2560) ep.gatepre[row * 2048 + (col - 512)] = v + ep.bfb[col - 512];
        else                 ep.gatesH[row * 2048 + (col - 2560)] = v + ep.bihh[col - 2560];
    } else {
        // batched preds: row = t*128 + b over Hall
        int t = row >> 7, b = row & 127;
        float mf = (t < ep.lens[b] - 1) ? 1.f : 0.f;
        ep.out_pred[((size_t)b * T + t) * V + col] = (v + ep.bfc[col]) * mf;
    }
}

// ============ packed-B split-f16 tensor GEMM: C = A(MxK,lda) @ Wpacked^T ============
#define PK_SMEM (2 * 65536)
__global__ __launch_bounds__(256, 1) void gemm_pk(
    const float* __restrict__ A, const uint8_t* __restrict__ Bp, float* __restrict__ C,
    int M, int N, int K, int lda, int kcTotal, EpiP ep)
{
    extern __shared__ char smem[];
    const uint32_t sbase = smem_u32(smem);
    const int tid = threadIdx.x, wid = tid >> 5, lane = tid & 31;
    const int bn = blockIdx.x * 128, bm = blockIdx.y * 128;
    const int z = blockIdx.z;
    const int Ks = K / (int)gridDim.z;
    const int nchunks = Ks >> 6;
    const int kchunk0 = (z * Ks) >> 6;

    const int r  = tid >> 1;
    const int c0 = (tid & 1) * 32;
    const float* aP = A + (size_t)(bm + r) * lda + (size_t)z * Ks + c0;
    const uint8_t* bBase = Bp + ((size_t)(bn >> 7) * kcTotal + kchunk0) * 32768
                         + (uint32_t)tid * 128;

    const int wm = wid & 3, wn = wid >> 2;
    const int m0 = wm * 32, n0w = wn * 64;
    const uint32_t arowb = (uint32_t)(m0 + (lane & 15)) * 128;
    const uint32_t acolp = ((lane >> 4) & 1) * 16;
    const uint32_t browb = (uint32_t)(n0w + (lane & 7) + ((lane & 16) ? 8 : 0)) * 128;
    const uint32_t bcolp = (lane & 8) ? 16u : 0u;

    float acc[2][8][4];
#pragma unroll
    for (int mi = 0; mi < 2; mi++)
#pragma unroll
        for (int ni = 0; ni < 8; ni++)
#pragma unroll
            for (int q = 0; q < 4; q++) acc[mi][ni][q] = 0.f;

    for (int ch = 0; ch < nchunks; ch++) {
        const int buf = ch & 1;
        const uint32_t base = (uint32_t)buf * 65536;
        if (ch >= 2) {
            asm volatile("bar.sync %0, %1;" :: "r"(1 + buf), "r"(512) : "memory");
        }
        {
            const uint8_t* bsrc = bBase + (size_t)ch * 32768;
            const uint32_t bdst = sbase + base + 32768 + (uint32_t)tid * 128;
#pragma unroll
            for (int j = 0; j < 8; j++) CP_ASYNC16(bdst + j * 16, bsrc + j * 16);
            asm volatile("cp.async.commit_group;" ::: "memory");
        }
        {
            const float* src = aP + ch * 64;
#pragma unroll
            for (int g = 0; g < 4; g++) {
                float4 v0 = *(const float4*)(src + g * 8);
                float4 v1 = *(const float4*)(src + g * 8 + 4);
                uint32_t h0, l0, h1, l1, h2, l2, h3, l3;
                conv2h(v0.x, v0.y, h0, l0); conv2h(v0.z, v0.w, h1, l1);
                conv2h(v1.x, v1.y, h2, l2); conv2h(v1.z, v1.w, h3, l3);
                uint32_t sw = swz((uint32_t)r * 128 + (uint32_t)(c0 + g * 8) * 2);
                *(uint4*)(smem + base + sw)         = make_uint4(h0, h1, h2, h3);
                *(uint4*)(smem + base + 16384 + sw) = make_uint4(l0, l1, l2, l3);
            }
        }
        asm volatile("cp.async.wait_group 0;" ::: "memory");
        __syncthreads();

        const uint32_t ahB = sbase + base;
        const uint32_t alB = ahB + 16384;
        const uint32_t bhB = ahB + 32768;
        const uint32_t blB = ahB + 49152;
#pragma unroll
        for (int ks = 0; ks < 4; ks++) {
            const uint32_t kb = (uint32_t)ks * 32;
            uint32_t ah[2][4], al[2][4];
#pragma unroll
            for (int mi = 0; mi < 2; mi++) {
                uint32_t ao = swz(arowb + (uint32_t)mi * 2048 + kb + acolp);
                ldsm4(ah[mi], ahB + ao);
                ldsm4(al[mi], alB + ao);
            }
            uint32_t bh[8][2], bl[8][2];
#pragma unroll
            for (int nj = 0; nj < 4; nj++) {
                uint32_t bo = swz(browb + (uint32_t)nj * 2048 + kb + bcolp);
                uint32_t t4[4];
                ldsm4(t4, bhB + bo);
                bh[2*nj][0] = t4[0]; bh[2*nj][1] = t4[1];
                bh[2*nj+1][0] = t4[2]; bh[2*nj+1][1] = t4[3];
                ldsm4(t4, blB + bo);
                bl[2*nj][0] = t4[0]; bl[2*nj][1] = t4[1];
                bl[2*nj+1][0] = t4[2]; bl[2*nj+1][1] = t4[3];
            }
#pragma unroll
            for (int mi = 0; mi < 2; mi++)
#pragma unroll
                for (int ni = 0; ni < 8; ni++) {
                    mma16816(acc[mi][ni], ah[mi], bh[ni]);
                    mma16816(acc[mi][ni], ah[mi], bl[ni]);
                    mma16816(acc[mi][ni], al[mi], bh[ni]);
                }
        }
        asm volatile("bar.arrive %0, %1;" :: "r"(1 + buf), "r"(512) : "memory");
    }

#pragma unroll
    for (int mi = 0; mi < 2; mi++) {
        const int row1 = bm + m0 + mi * 16 + (lane >> 2);
        const int row2 = row1 + 8;
#pragma unroll
        for (int ni = 0; ni < 8; ni++) {
            const int col = bn + n0w + ni * 8 + 2 * (lane & 3);
            epi_store(ep, C, M, N, z, row1, col,     acc[mi][ni][0]);
            epi_store(ep, C, M, N, z, row1, col + 1, acc[mi][ni][1]);
            epi_store(ep, C, M, N, z, row2, col,     acc[mi][ni][2]);
            epi_store(ep, C, M, N, z, row2, col + 1, acc[mi][ni][3]);
        }
    }
}

// ---------------- small kernels ----------------
__global__ void enc2h_kernel(const float* __restrict__ enc, __half* __restrict__ ench) {
    size_t i = ((size_t)blockIdx.x * 256 + threadIdx.x) * 8;   // grid (B*P*F/2048)
    float4 v0 = *(const float4*)(enc + i);
    float4 v1 = *(const float4*)(enc + i + 4);
    __half2 h0 = __floats2half2_rn(v0.x, v0.y);
    __half2 h1 = __floats2half2_rn(v0.z, v0.w);
    __half2 h2 = __floats2half2_rn(v1.x, v1.y);
    __half2 h3 = __floats2half2_rn(v1.z, v1.w);
    *(uint4*)(ench + i) = make_uint4(h2u(h0), h2u(h1), h2u(h2), h2u(h3));
}

__global__ void mean_kernel(const float* __restrict__ enc, float* __restrict__ feat) {
    int f = blockIdx.x * 256 + threadIdx.x;   // grid (8, B)
    int b = blockIdx.y;
    const float* p0 = enc + (size_t)b * P * F + f;
    float s = 0.f;
#pragma unroll 4
    for (int p = 0; p < P; p++) s += p0[(size_t)p * F];
    feat[b * F + f] = s * (1.0f / (float)P);
}

__global__ void bihh_kernel(const float* __restrict__ bih, const float* __restrict__ bhh,
                            float* __restrict__ out) {
    int n = blockIdx.x * 256 + threadIdx.x;
    out[n] = bih[n] + bhh[n];
}

__global__ void embgather_kernel(const float* __restrict__ emb, const int* __restrict__ caps,
                                 float* __restrict__ embseq) {
    int col = blockIdx.x * 256 + threadIdx.x; // grid (2, T*B)
    int rrow = blockIdx.y;
    int t = rrow / B, b = rrow % B;
    int tok = caps[b * L + t];
    embseq[(size_t)rrow * E + col] = emb[(size_t)tok * E + col];
}

// fused h0+c0 epilogue over the combined N=1024 GEMM (S=4 partials)
__global__ void epi_hc2_kernel(const float* __restrict__ part,
                               const float* __restrict__ bh0, const float* __restrict__ bc0,
                               const float* __restrict__ gamma_h, const float* __restrict__ beta_h,
                               const float* __restrict__ gamma_c, const float* __restrict__ beta_c,
                               float* __restrict__ h0, float* __restrict__ c) {
    int n = blockIdx.x * 256 + threadIdx.x;   // grid (4, B), n in [0,1024)
    int m = blockIdx.y;
    float s = 0.f;
#pragma unroll
    for (int zz = 0; zz < 4; zz++) s += part[(size_t)zz * B * 1024 + m * 1024 + n];
    if (n < 512) {
        float x = sigmoidf(s + bh0[n]);
        h0[m * 512 + n] = gamma_h[n] * (x * BN_SCALE) + beta_h[n];
    } else {
        int j = n - 512;
        float x = sigmoidf(s + bc0[j]);
        c[m * 512 + j] = gamma_c[j] * (x * BN_SCALE) + beta_c[j];
    }
}

// e[b,p] = sum_n relu(fa[b,p,n] + hWha[b,n]) * Wv[n]   (bv dropped; cancels in softmax)
__global__ __launch_bounds__(256) void att_e_kernel(
    const float* __restrict__ fa, const float* __restrict__ hw,
    const float* __restrict__ Wv, float* __restrict__ e) {
    int warp = threadIdx.x >> 5, lane = threadIdx.x & 31;
    int gid = blockIdx.x * 8 + warp;          // grid (B*P/8) = 3136 warps
    int b = gid / P;
    const float4* fav = (const float4*)(fa + (size_t)gid * NF);
    const float4* hwv = (const float4*)(hw + (size_t)b * NF);
    const float4* wvv = (const float4*)Wv;
    float s = 0.f;
#pragma unroll
    for (int rr = 0; rr < 4; rr++) {
        int i = lane + rr * 32;
        float4 x = fav[i], y = hwv[i], w = wvv[i];
        s += fmaxf(x.x + y.x, 0.f) * w.x + fmaxf(x.y + y.y, 0.f) * w.y
           + fmaxf(x.z + y.z, 0.f) * w.z + fmaxf(x.w + y.w, 0.f) * w.w;
    }
#pragma unroll
    for (int o = 16; o; o >>= 1) s += __shfl_xor_sync(0xffffffffu, s, o);
    if (lane == 0) e[gid] = s;
}

// fused: softmax over e row + context over P (fp16 enc) + gate; bx==0 writes out_alpha
__global__ __launch_bounds__(256) void ctx_gate_kernel(
    const __half* __restrict__ ench, const float* __restrict__ e,
    const float* __restrict__ gatepre, float* __restrict__ xgc,
    float* __restrict__ out_alpha, const int* __restrict__ lens, int t) {
    __shared__ float red[256];
    __shared__ float sa[P];
    int b = blockIdx.y;                       // grid (4, B)
    int tid = threadIdx.x;
    // softmax over e[b, :]
    float v = (tid < P) ? e[b * P + tid] : -1e30f;
    red[tid] = v; __syncthreads();
    for (int o = 128; o; o >>= 1) { if (tid < o) red[tid] = fmaxf(red[tid], red[tid + o]); __syncthreads(); }
    float mx = red[0]; __syncthreads();
    float ex = (tid < P) ? expf(v - mx) : 0.f;
    red[tid] = ex; __syncthreads();
    for (int o = 128; o; o >>= 1) { if (tid < o) red[tid] += red[tid + o]; __syncthreads(); }
    float inv = 1.0f / red[0];
    float a = ex * inv;
    if (tid < P) {
        sa[tid] = a;
        if (blockIdx.x == 0) {
            float mf = (t < lens[b] - 1) ? 1.f : 0.f;
            out_alpha[((size_t)b * T + t) * P + tid] = a * mf;
        }
    }
    __syncthreads();
    // context + gate
    int f2 = blockIdx.x * 256 + tid;          // half2 column index
    const __half2* ep = (const __half2*)(ench + (size_t)b * P * F) + f2;
    float ax = 0.f, ay = 0.f;
#pragma unroll 8
    for (int p = 0; p < P; p++) {
        float2 vv = __half22float2(ep[(size_t)p * (F / 2)]);
        float aa = sa[p];
        ax += vv.x * aa; ay += vv.y * aa;
    }
    int idx = b * F + f2 * 2;
    xgc[idx]     = sigmoidf(gatepre[idx])     * ax;
    xgc[idx + 1] = sigmoidf(gatepre[idx + 1]) * ay;
}

// sums S=8 partials of xgc@WihF^T, adds gatesH + embW[t], runs LSTM cell
__global__ void lstm_epi_kernel(const float* __restrict__ part, const float* __restrict__ gatesH,
                                const float* __restrict__ embW, float* __restrict__ c,
                                float* __restrict__ hnext, int t) {
    int idx = blockIdx.x * 256 + threadIdx.x; // grid (B*H/256)
    int b = idx >> 9, j = idx & 511;
    float g4[4];
#pragma unroll
    for (int gi = 0; gi < 4; gi++) {
        int col = gi * 512 + j;
        float s = gatesH[b * 2048 + col] + embW[((size_t)t * B + b) * 2048 + col];
#pragma unroll
        for (int zz = 0; zz < 8; zz++) s += part[(size_t)zz * B * 2048 + b * 2048 + col];
        g4[gi] = s;
    }
    float ig = sigmoidf(g4[0]), fg = sigmoidf(g4[1]);
    float gg = tanhf(g4[2]),    og = sigmoidf(g4[3]);
    float cn = fg * c[idx] + ig * gg;
    c[idx] = cn;
    hnext[idx] = og * tanhf(cn);
}

// ---------------- host ----------------
static EpiP ep_partial() { EpiP e = {}; e.mode = 0; return e; }
static EpiP ep_bias(const float* bias) { EpiP e = {}; e.mode = 1; e.bias = bias; return e; }

static void gemm_launch(const float* A, const uint8_t* Bp, float* C, int M, int N, int K,
                        int lda, int kcTotal, int S, EpiP ep) {
    dim3 grid((N + 127) / 128, M / 128, S);
    gemm_pk<<<grid, 256, PK_SMEM>>>(A, Bp, C, M, N, K, lda, kcTotal, ep);
}

extern "C" void kernel_launch(void* const* d_in, const int* in_sizes, int n_in,
                              void* d_out, int out_size) {
    const float* enc     = (const float*)d_in[0];
    const float* emb     = (const float*)d_in[1];
    const float* Wfa     = (const float*)d_in[2];
    const float* bfa     = (const float*)d_in[3];
    const float* Wha     = (const float*)d_in[4];
    const float* bha     = (const float*)d_in[5];
    const float* Wv      = (const float*)d_in[6];
    // d_in[7] = bv (cancels in softmax)
    const float* Wh0     = (const float*)d_in[8];
    const float* bh0     = (const float*)d_in[9];
    const float* Wc0     = (const float*)d_in[10];
    const float* bc0     = (const float*)d_in[11];
    const float* gamma_h = (const float*)d_in[12];
    const float* beta_h  = (const float*)d_in[13];
    const float* gamma_c = (const float*)d_in[14];
    const float* beta_c  = (const float*)d_in[15];
    const float* Wfb     = (const float*)d_in[16];
    const float* bfb     = (const float*)d_in[17];
    const float* Wih     = (const float*)d_in[18];
    const float* Whh     = (const float*)d_in[19];
    const float* bih     = (const float*)d_in[20];
    const float* bhh     = (const float*)d_in[21];
    const float* Wfc     = (const float*)d_in[22];
    const float* bfc     = (const float*)d_in[23];
    const int*   caps    = (const int*)d_in[24];
    const int*   lens    = (const int*)d_in[25];

    float* out_pred  = (float*)d_out;
    float* out_alpha = out_pred + (size_t)B * T * V;

    cudaFuncSetAttribute(gemm_pk, cudaFuncAttributeMaxDynamicSharedMemorySize, PK_SMEM);

    float *p_feat, *p_fa, *p_h0, *p_Hall, *p_c, *p_hW, *p_e, *p_gp, *p_gH, *p_xgc,
          *p_bb, *p_es, *p_eW, *p_part;
    __half* p_ench;
    uint8_t *pk_wcat4, *pk_wihF, *pk_wihE, *pk_wfa, *pk_whc0;
    cudaGetSymbolAddress((void**)&p_feat, g_feat);
    cudaGetSymbolAddress((void**)&p_fa,   g_feat_att);
    cudaGetSymbolAddress((void**)&p_h0,   g_h0);
    cudaGetSymbolAddress((void**)&p_Hall, g_Hall);
    cudaGetSymbolAddress((void**)&p_c,    g_c);
    cudaGetSymbolAddress((void**)&p_hW,   g_hWha);
    cudaGetSymbolAddress((void**)&p_e,    g_e);
    cudaGetSymbolAddress((void**)&p_gp,   g_gatepre);
    cudaGetSymbolAddress((void**)&p_gH,   g_gatesH);
    cudaGetSymbolAddress((void**)&p_xgc,  g_xgc);
    cudaGetSymbolAddress((void**)&p_bb,   g_bihh);
    cudaGetSymbolAddress((void**)&p_es,   g_embseq);
    cudaGetSymbolAddress((void**)&p_eW,   g_embW);
    cudaGetSymbolAddress((void**)&p_part, g_part);
    cudaGetSymbolAddress((void**)&p_ench, g_ench);
    cudaGetSymbolAddress((void**)&pk_wcat4, g_pk_wcat4);
    cudaGetSymbolAddress((void**)&pk_wihF, g_pk_wihF);
    cudaGetSymbolAddress((void**)&pk_wihE, g_pk_wihE);
    cudaGetSymbolAddress((void**)&pk_wfa, g_pk_wfa);
    cudaGetSymbolAddress((void**)&pk_whc0, g_pk_whc0);

    // ---- precompute ----
    enc2h_kernel<<<dim3((int)(((size_t)B * P * F) / 2048)), 256>>>(enc, p_ench);
    pack_kernel<<<dim3(4, 32), 256>>>(Wfa, pk_wfa, NF, F);
    pack_kernel<<<dim3(4, 32), 256>>>(Wh0, pk_whc0, H, F);
    pack_kernel<<<dim3(4, 32), 256>>>(Wc0, pk_whc0 + (size_t)4 * 32 * 32768, H, F);
    pack_kernel<<<dim3(16, 8), 256>>>(Wih, pk_wihE, 4 * H, E + F);
    pack_kernel<<<dim3(16, 32), 256>>>(Wih + E, pk_wihF, 4 * H, E + F);
    pack_kernel<<<dim3(4, 8), 256>>>(Wha, pk_wcat4, 512, H);
    pack_kernel<<<dim3(16, 8), 256>>>(Wfb, pk_wcat4 + (size_t)4 * 8 * 32768, 2048, H);
    pack_kernel<<<dim3(16, 8), 256>>>(Whh, pk_wcat4 + (size_t)20 * 8 * 32768, 2048, H);
    pack_kernel<<<dim3(79, 8), 256>>>(Wfc, pk_wcat4 + (size_t)36 * 8 * 32768, V, H);

    mean_kernel<<<dim3(F / 256, B), 256>>>(enc, p_feat);
    bihh_kernel<<<dim3(4 * H / 256), 256>>>(bih, bhh, p_bb);
    embgather_kernel<<<dim3(E / 256, T * B), 256>>>(emb, caps, p_es);

    // h0 & c0 fused: feat @ [Wh0|Wc0]^T (N=1024, K=2048, S=4 partials)
    gemm_launch(p_feat, pk_whc0, p_part, B, 1024, F, F, 32, 4, ep_partial());
    epi_hc2_kernel<<<dim3(4, B), 256>>>(p_part, bh0, bc0, gamma_h, beta_h, gamma_c, beta_c,
                                        p_h0, p_c);

    // embW = embseq(2432x512) @ Wih[:, :E]^T
    gemm_launch(p_es, pk_wihE, p_eW, T * B, 4 * H, E, E, 8, 1, ep_bias(nullptr));

    // feat_att = enc(25088x2048) @ Wfa^T + bfa
    gemm_launch(enc, pk_wfa, p_fa, B * P, NF, F, F, 32, 1, ep_bias(bfa));

    // initial h-side projections from h0 (mode 2 scatter => S=1 ONLY)
    {
        EpiP ep = {}; ep.mode = 2;
        ep.bha = bha; ep.bfb = bfb; ep.bihh = p_bb;
        ep.hWha = p_hW; ep.gatepre = p_gp; ep.gatesH = p_gH;
        gemm_launch(p_h0, pk_wcat4, nullptr, B, NCOMBO, H, H, 8, 1, ep);
    }

    // ---- timestep loop: 5 launches per step (4 at t=T-1) ----
    for (int t = 0; t < T; t++) {
        att_e_kernel<<<dim3(B * P / 8), 256>>>(p_fa, p_hW, Wv, p_e);
        ctx_gate_kernel<<<dim3(F / 512, B), 256>>>(p_ench, p_e, p_gp, p_xgc,
                                                   out_alpha, lens, t);

        // xgc @ Wih[:, E:]^T  (N=2048, K=2048, S=8 -> 128 CTAs)
        gemm_launch(p_xgc, pk_wihF, p_part, B, 4 * H, F, F, 32, 8, ep_partial());
        lstm_epi_kernel<<<dim3(B * H / 256), 256>>>(p_part, p_gH, p_eW, p_c,
                                                    p_Hall + (size_t)t * B * H, t);

        if (t + 1 < T) {
            // combo: h_{t+1} @ [Wha|Wfb|Whh]^T (mode 2 scatter => S=1 ONLY)
            EpiP ep = {}; ep.mode = 2;
            ep.bha = bha; ep.bfb = bfb; ep.bihh = p_bb;
            ep.hWha = p_hW; ep.gatepre = p_gp; ep.gatesH = p_gH;
            gemm_launch(p_Hall + (size_t)t * B * H, pk_wcat4, nullptr, B, NCOMBO, H, H, 8, 1, ep);
        }
    }

    // ---- batched preds: Hall(2432x512) @ Wfc^T (10000), masked strided store ----
    {
        EpiP ep = {}; ep.mode = 3;
        ep.bfc = bfc; ep.lens = lens; ep.out_pred = out_pred;
        gemm_launch(p_Hall, pk_wcat4 + (size_t)36 * 8 * 32768, nullptr,
                    T * B, V, H, H, 8, 1, ep);
    }
}

// round 16
// speedup vs baseline: 1.1240x; 1.1240x over previous
#include <cuda_runtime.h>
#include <cuda_fp16.h>
#include <cstdint>
#include <cstddef>

#define B 128
#define P 196
#define F 2048
#define H 512
#define NF 512
#define E 512
#define V 10000
#define L 20
#define T 19
#define NCOMBO 14608      // 512 (Wha) + 2048 (Wfb) + 2048 (Whh) + 10000 (Wfc)
#define BN_SCALE 0.9999950000374997f   // 1/sqrt(1+1e-5)

typedef unsigned long long ull;

// ---------------- scratch (static device globals) ----------------
__device__ float g_feat[B * F];
__device__ float g_feat_att[(size_t)B * P * NF];       // 51.4 MB
__device__ float g_hbuf[B * H];
__device__ float g_c[B * H];
__device__ float g_hWha[B * NF];
__device__ float g_e[B * P];
__device__ float g_gatepre[B * F];
__device__ float g_gatesH[B * 4 * H];
__device__ float g_xgc[B * F];
__device__ float g_bihh[4 * H];
__device__ float g_embseq[(size_t)T * B * E];
__device__ float g_embW[(size_t)T * B * 4 * H];        // 19.9 MB
__device__ float g_part[4 * 1024 * 1024];              // split-K partials (16 MB)
__device__ __half g_ench[(size_t)B * P * F];           // fp16 enc copy, 102.8 MB

// packed hi/lo f16 weight planes (pre-swizzled smem images, 32 KB per (nblk,chunk))
__device__ uint8_t g_pk_wcat4[(size_t)115 * 8 * 32768];   // [Wha|Wfb|Whh|Wfc] 30.1 MB
__device__ uint8_t g_pk_wihF[(size_t)16 * 32 * 32768];    // 16.8 MB
__device__ uint8_t g_pk_wihE[(size_t)16 * 8 * 32768];     // 4.2 MB
__device__ uint8_t g_pk_wfa[(size_t)4 * 32 * 32768];      // 4.2 MB
__device__ uint8_t g_pk_whc0[(size_t)8 * 32 * 32768];     // [Wh0|Wc0] 8.4 MB

__device__ __forceinline__ float sigmoidf(float x) { return 1.0f / (1.0f + expf(-x)); }

__device__ __forceinline__ uint32_t h2u(__half2 h) {
    uint32_t u;
    memcpy(&u, &h, 4);
    return u;
}

// ---------------- mma.sync helpers (non-'a' ISA) ----------------
__device__ __forceinline__ uint32_t smem_u32(const void* p) {
    uint32_t a;
    asm("{ .reg .u64 t; cvta.to.shared.u64 t, %1; cvt.u32.u64 %0, t; }" : "=r"(a) : "l"(p));
    return a;
}
__device__ __forceinline__ void ldsm4(uint32_t* r, uint32_t addr) {
    asm volatile("ldmatrix.sync.aligned.m8n8.x4.shared.b16 {%0,%1,%2,%3}, [%4];"
                 : "=r"(r[0]), "=r"(r[1]), "=r"(r[2]), "=r"(r[3]) : "r"(addr));
}
__device__ __forceinline__ void mma16816(float* c, const uint32_t* a, const uint32_t* b) {
    asm volatile(
        "mma.sync.aligned.m16n8k16.row.col.f32.f16.f16.f32 "
        "{%0,%1,%2,%3}, {%4,%5,%6,%7}, {%8,%9}, {%0,%1,%2,%3};"
        : "+f"(c[0]), "+f"(c[1]), "+f"(c[2]), "+f"(c[3])
        : "r"(a[0]), "r"(a[1]), "r"(a[2]), "r"(a[3]), "r"(b[0]), "r"(b[1]));
}
__device__ __forceinline__ uint32_t swz(uint32_t off) { return off ^ ((off >> 3) & 0x70); }
#define CP_ASYNC16(saddr, gaddr) \
    asm volatile("cp.async.cg.shared.global [%0], [%1], 16;" :: "r"(saddr), "l"(gaddr))

// split fp32 pair -> f16x2 hi word + f16x2 lo word
__device__ __forceinline__ void conv2h(float x, float y, uint32_t& hw, uint32_t& lw) {
    __half hx = __float2half_rn(x), hy = __float2half_rn(y);
    float rx = x - __half2float(hx);
    float ry = y - __half2float(hy);
    __half lx = __float2half_rn(rx), ly = __float2half_rn(ry);
    hw = ((uint32_t)__half_as_ushort(hy) << 16) | (uint32_t)__half_as_ushort(hx);
    lw = ((uint32_t)__half_as_ushort(ly) << 16) | (uint32_t)__half_as_ushort(lx);
}

// ---------------- weight pack kernel: fp32 (NxK,ldb) -> hi/lo planes, swizzled ------
__global__ void pack_kernel(const float* __restrict__ src, uint8_t* __restrict__ dst,
                            int N, int ldb) {
    int nblk = blockIdx.x, chunk = blockIdx.y, tid = threadIdx.x;
    int r = tid >> 1, c0 = (tid & 1) * 32;
    int row = nblk * 128 + r;
    bool ok = row < N;
    const float* s = src + (size_t)row * ldb + chunk * 64 + c0;
    uint8_t* base = dst + ((size_t)nblk * gridDim.y + chunk) * 32768;
#pragma unroll
    for (int g = 0; g < 4; g++) {
        float4 v0 = ok ? *(const float4*)(s + g * 8)     : make_float4(0.f, 0.f, 0.f, 0.f);
        float4 v1 = ok ? *(const float4*)(s + g * 8 + 4) : make_float4(0.f, 0.f, 0.f, 0.f);
        uint32_t h0, l0, h1, l1, h2, l2, h3, l3;
        conv2h(v0.x, v0.y, h0, l0); conv2h(v0.z, v0.w, h1, l1);
        conv2h(v1.x, v1.y, h2, l2); conv2h(v1.z, v1.w, h3, l3);
        uint32_t sw = swz((uint32_t)r * 128 + (uint32_t)(c0 + g * 8) * 2);
        *(uint4*)(base + sw)         = make_uint4(h0, h1, h2, h3);
        *(uint4*)(base + 16384 + sw) = make_uint4(l0, l1, l2, l3);
    }
}

// ---------------- epilogue param block ----------------
struct EpiP {
    int mode;            // 0 partial, 1 bias-direct, 2 combo-scatter+preds (S==1 ONLY)
    const float* bias;   // mode 1
    const float* bha; const float* bfb; const float* bihh; const float* bfc;
    const int* lens; int t;
    float* hWha; float* gatepre; float* gatesH; float* out_pred;
};

__device__ __forceinline__ void epi_store(const EpiP& ep, float* C, int M, int N, int z,
                                          int row, int col, float v) {
    if (col >= N) return;
    if (ep.mode == 0) {
        C[(size_t)z * M * N + (size_t)row * N + col] = v;
    } else if (ep.mode == 1) {
        C[(size_t)row * N + col] = ep.bias ? v + ep.bias[col] : v;
    } else {
        if (col < 512)       ep.hWha[row * 512 + col] = v + ep.bha[col];
        else if (col < 2560) ep.gatepre[row * 2048 + (col - 512)] = v + ep.bfb[col - 512];
        else if (col < 4608) ep.gatesH[row * 2048 + (col - 2560)] = v + ep.bihh[col - 2560];
        else {
            int n = col - 4608;
            float mf = (ep.t < ep.lens[row] - 1) ? 1.f : 0.f;
            ep.out_pred[((size_t)row * T + ep.t) * V + n] = (v + ep.bfc[n]) * mf;
        }
    }
}

// ============ packed-B split-f16 tensor GEMM: C = A(MxK,lda) @ Wpacked^T ============
#define PK_SMEM (2 * 65536)
__global__ __launch_bounds__(256, 1) void gemm_pk(
    const float* __restrict__ A, const uint8_t* __restrict__ Bp, float* __restrict__ C,
    int M, int N, int K, int lda, int kcTotal, EpiP ep)
{
    extern __shared__ char smem[];
    const uint32_t sbase = smem_u32(smem);
    const int tid = threadIdx.x, wid = tid >> 5, lane = tid & 31;
    const int bn = blockIdx.x * 128, bm = blockIdx.y * 128;
    const int z = blockIdx.z;
    const int Ks = K / (int)gridDim.z;
    const int nchunks = Ks >> 6;
    const int kchunk0 = (z * Ks) >> 6;

    const int r  = tid >> 1;
    const int c0 = (tid & 1) * 32;
    const float* aP = A + (size_t)(bm + r) * lda + (size_t)z * Ks + c0;
    const uint8_t* bBase = Bp + ((size_t)(bn >> 7) * kcTotal + kchunk0) * 32768
                         + (uint32_t)tid * 128;

    const int wm = wid & 3, wn = wid >> 2;
    const int m0 = wm * 32, n0w = wn * 64;
    const uint32_t arowb = (uint32_t)(m0 + (lane & 15)) * 128;
    const uint32_t acolp = ((lane >> 4) & 1) * 16;
    const uint32_t browb = (uint32_t)(n0w + (lane & 7) + ((lane & 16) ? 8 : 0)) * 128;
    const uint32_t bcolp = (lane & 8) ? 16u : 0u;

    float acc[2][8][4];
#pragma unroll
    for (int mi = 0; mi < 2; mi++)
#pragma unroll
        for (int ni = 0; ni < 8; ni++)
#pragma unroll
            for (int q = 0; q < 4; q++) acc[mi][ni][q] = 0.f;

    for (int ch = 0; ch < nchunks; ch++) {
        const int buf = ch & 1;
        const uint32_t base = (uint32_t)buf * 65536;
        if (ch >= 2) {
            asm volatile("bar.sync %0, %1;" :: "r"(1 + buf), "r"(512) : "memory");
        }
        {
            const uint8_t* bsrc = bBase + (size_t)ch * 32768;
            const uint32_t bdst = sbase + base + 32768 + (uint32_t)tid * 128;
#pragma unroll
            for (int j = 0; j < 8; j++) CP_ASYNC16(bdst + j * 16, bsrc + j * 16);
            asm volatile("cp.async.commit_group;" ::: "memory");
        }
        {
            const float* src = aP + ch * 64;
#pragma unroll
            for (int g = 0; g < 4; g++) {
                float4 v0 = *(const float4*)(src + g * 8);
                float4 v1 = *(const float4*)(src + g * 8 + 4);
                uint32_t h0, l0, h1, l1, h2, l2, h3, l3;
                conv2h(v0.x, v0.y, h0, l0); conv2h(v0.z, v0.w, h1, l1);
                conv2h(v1.x, v1.y, h2, l2); conv2h(v1.z, v1.w, h3, l3);
                uint32_t sw = swz((uint32_t)r * 128 + (uint32_t)(c0 + g * 8) * 2);
                *(uint4*)(smem + base + sw)         = make_uint4(h0, h1, h2, h3);
                *(uint4*)(smem + base + 16384 + sw) = make_uint4(l0, l1, l2, l3);
            }
        }
        asm volatile("cp.async.wait_group 0;" ::: "memory");
        __syncthreads();

        const uint32_t ahB = sbase + base;
        const uint32_t alB = ahB + 16384;
        const uint32_t bhB = ahB + 32768;
        const uint32_t blB = ahB + 49152;
#pragma unroll
        for (int ks = 0; ks < 4; ks++) {
            const uint32_t kb = (uint32_t)ks * 32;
            uint32_t ah[2][4], al[2][4];
#pragma unroll
            for (int mi = 0; mi < 2; mi++) {
                uint32_t ao = swz(arowb + (uint32_t)mi * 2048 + kb + acolp);
                ldsm4(ah[mi], ahB + ao);
                ldsm4(al[mi], alB + ao);
            }
            uint32_t bh[8][2], bl[8][2];
#pragma unroll
            for (int nj = 0; nj < 4; nj++) {
                uint32_t bo = swz(browb + (uint32_t)nj * 2048 + kb + bcolp);
                uint32_t t4[4];
                ldsm4(t4, bhB + bo);
                bh[2*nj][0] = t4[0]; bh[2*nj][1] = t4[1];
                bh[2*nj+1][0] = t4[2]; bh[2*nj+1][1] = t4[3];
                ldsm4(t4, blB + bo);
                bl[2*nj][0] = t4[0]; bl[2*nj][1] = t4[1];
                bl[2*nj+1][0] = t4[2]; bl[2*nj+1][1] = t4[3];
            }
#pragma unroll
            for (int mi = 0; mi < 2; mi++)
#pragma unroll
                for (int ni = 0; ni < 8; ni++) {
                    mma16816(acc[mi][ni], ah[mi], bh[ni]);
                    mma16816(acc[mi][ni], ah[mi], bl[ni]);
                    mma16816(acc[mi][ni], al[mi], bh[ni]);
                }
        }
        asm volatile("bar.arrive %0, %1;" :: "r"(1 + buf), "r"(512) : "memory");
    }

#pragma unroll
    for (int mi = 0; mi < 2; mi++) {
        const int row1 = bm + m0 + mi * 16 + (lane >> 2);
        const int row2 = row1 + 8;
#pragma unroll
        for (int ni = 0; ni < 8; ni++) {
            const int col = bn + n0w + ni * 8 + 2 * (lane & 3);
            epi_store(ep, C, M, N, z, row1, col,     acc[mi][ni][0]);
            epi_store(ep, C, M, N, z, row1, col + 1, acc[mi][ni][1]);
            epi_store(ep, C, M, N, z, row2, col,     acc[mi][ni][2]);
            epi_store(ep, C, M, N, z, row2, col + 1, acc[mi][ni][3]);
        }
    }
}

// ---------------- small kernels ----------------
__global__ void enc2h_kernel(const float* __restrict__ enc, __half* __restrict__ ench) {
    size_t i = ((size_t)blockIdx.x * 256 + threadIdx.x) * 8;   // grid (B*P*F/2048)
    float4 v0 = *(const float4*)(enc + i);
    float4 v1 = *(const float4*)(enc + i + 4);
    __half2 h0 = __floats2half2_rn(v0.x, v0.y);
    __half2 h1 = __floats2half2_rn(v0.z, v0.w);
    __half2 h2 = __floats2half2_rn(v1.x, v1.y);
    __half2 h3 = __floats2half2_rn(v1.z, v1.w);
    *(uint4*)(ench + i) = make_uint4(h2u(h0), h2u(h1), h2u(h2), h2u(h3));
}

__global__ void mean_kernel(const float* __restrict__ enc, float* __restrict__ feat) {
    int f = blockIdx.x * 256 + threadIdx.x;   // grid (8, B)
    int b = blockIdx.y;
    const float* p0 = enc + (size_t)b * P * F + f;
    float s = 0.f;
#pragma unroll 4
    for (int p = 0; p < P; p++) s += p0[(size_t)p * F];
    feat[b * F + f] = s * (1.0f / (float)P);
}

__global__ void bihh_kernel(const float* __restrict__ bih, const float* __restrict__ bhh,
                            float* __restrict__ out) {
    int n = blockIdx.x * 256 + threadIdx.x;
    out[n] = bih[n] + bhh[n];
}

__global__ void embgather_kernel(const float* __restrict__ emb, const int* __restrict__ caps,
                                 float* __restrict__ embseq) {
    int col = blockIdx.x * 256 + threadIdx.x; // grid (2, T*B)
    int rrow = blockIdx.y;
    int t = rrow / B, b = rrow % B;
    int tok = caps[b * L + t];
    embseq[(size_t)rrow * E + col] = emb[(size_t)tok * E + col];
}

// fused h0+c0 epilogue over the combined N=1024 GEMM (S=4 partials)
__global__ void epi_hc2_kernel(const float* __restrict__ part,
                               const float* __restrict__ bh0, const float* __restrict__ bc0,
                               const float* __restrict__ gamma_h, const float* __restrict__ beta_h,
                               const float* __restrict__ gamma_c, const float* __restrict__ beta_c,
                               float* __restrict__ h0, float* __restrict__ c) {
    int n = blockIdx.x * 256 + threadIdx.x;   // grid (4, B), n in [0,1024)
    int m = blockIdx.y;
    float s = 0.f;
#pragma unroll
    for (int zz = 0; zz < 4; zz++) s += part[(size_t)zz * B * 1024 + m * 1024 + n];
    if (n < 512) {
        float x = sigmoidf(s + bh0[n]);
        h0[m * 512 + n] = gamma_h[n] * (x * BN_SCALE) + beta_h[n];
    } else {
        int j = n - 512;
        float x = sigmoidf(s + bc0[j]);
        c[m * 512 + j] = gamma_c[j] * (x * BN_SCALE) + beta_c[j];
    }
}

// e[b,p] = sum_n relu(fa[b,p,n] + hWha[b,n]) * Wv[n]   (bv dropped; cancels in softmax)
__global__ __launch_bounds__(256) void att_e_kernel(
    const float* __restrict__ fa, const float* __restrict__ hw,
    const float* __restrict__ Wv, float* __restrict__ e) {
    int warp = threadIdx.x >> 5, lane = threadIdx.x & 31;
    int gid = blockIdx.x * 8 + warp;          // grid (B*P/8) = 3136 warps
    int b = gid / P;
    const float4* fav = (const float4*)(fa + (size_t)gid * NF);
    const float4* hwv = (const float4*)(hw + (size_t)b * NF);
    const float4* wvv = (const float4*)Wv;
    float s = 0.f;
#pragma unroll
    for (int rr = 0; rr < 4; rr++) {
        int i = lane + rr * 32;
        float4 x = fav[i], y = hwv[i], w = wvv[i];
        s += fmaxf(x.x + y.x, 0.f) * w.x + fmaxf(x.y + y.y, 0.f) * w.y
           + fmaxf(x.z + y.z, 0.f) * w.z + fmaxf(x.w + y.w, 0.f) * w.w;
    }
#pragma unroll
    for (int o = 16; o; o >>= 1) s += __shfl_xor_sync(0xffffffffu, s, o);
    if (lane == 0) e[gid] = s;
}

// fused: softmax over e row + context over P (fp16 enc) + gate; bx==0 writes out_alpha
__global__ __launch_bounds__(256) void ctx_gate_kernel(
    const __half* __restrict__ ench, const float* __restrict__ e,
    const float* __restrict__ gatepre, float* __restrict__ xgc,
    float* __restrict__ out_alpha, const int* __restrict__ lens, int t) {
    __shared__ float red[256];
    __shared__ float sa[P];
    int b = blockIdx.y;                       // grid (4, B)
    int tid = threadIdx.x;
    // softmax over e[b, :]
    float v = (tid < P) ? e[b * P + tid] : -1e30f;
    red[tid] = v; __syncthreads();
    for (int o = 128; o; o >>= 1) { if (tid < o) red[tid] = fmaxf(red[tid], red[tid + o]); __syncthreads(); }
    float mx = red[0]; __syncthreads();
    float ex = (tid < P) ? expf(v - mx) : 0.f;
    red[tid] = ex; __syncthreads();
    for (int o = 128; o; o >>= 1) { if (tid < o) red[tid] += red[tid + o]; __syncthreads(); }
    float inv = 1.0f / red[0];
    float a = ex * inv;
    if (tid < P) {
        sa[tid] = a;
        if (blockIdx.x == 0) {
            float mf = (t < lens[b] - 1) ? 1.f : 0.f;
            out_alpha[((size_t)b * T + t) * P + tid] = a * mf;
        }
    }
    __syncthreads();
    // context + gate
    int f2 = blockIdx.x * 256 + tid;          // half2 column index
    const __half2* ep = (const __half2*)(ench + (size_t)b * P * F) + f2;
    float ax = 0.f, ay = 0.f;
#pragma unroll 8
    for (int p = 0; p < P; p++) {
        float2 vv = __half22float2(ep[(size_t)p * (F / 2)]);
        float aa = sa[p];
        ax += vv.x * aa; ay += vv.y * aa;
    }
    int idx = b * F + f2 * 2;
    xgc[idx]     = sigmoidf(gatepre[idx])     * ax;
    xgc[idx + 1] = sigmoidf(gatepre[idx + 1]) * ay;
}

// sums S=8 partials of xgc@WihF^T, adds gatesH + embW[t], runs LSTM cell
__global__ void lstm_epi_kernel(const float* __restrict__ part, const float* __restrict__ gatesH,
                                const float* __restrict__ embW, float* __restrict__ c,
                                float* __restrict__ hnext, int t) {
    int idx = blockIdx.x * 256 + threadIdx.x; // grid (B*H/256)
    int b = idx >> 9, j = idx & 511;
    float g4[4];
#pragma unroll
    for (int gi = 0; gi < 4; gi++) {
        int col = gi * 512 + j;
        float s = gatesH[b * 2048 + col] + embW[((size_t)t * B + b) * 2048 + col];
#pragma unroll
        for (int zz = 0; zz < 8; zz++) s += part[(size_t)zz * B * 2048 + b * 2048 + col];
        g4[gi] = s;
    }
    float ig = sigmoidf(g4[0]), fg = sigmoidf(g4[1]);
    float gg = tanhf(g4[2]),    og = sigmoidf(g4[3]);
    float cn = fg * c[idx] + ig * gg;
    c[idx] = cn;
    hnext[idx] = og * tanhf(cn);
}

// ---------------- host ----------------
static EpiP ep_partial() { EpiP e = {}; e.mode = 0; return e; }
static EpiP ep_bias(const float* bias) { EpiP e = {}; e.mode = 1; e.bias = bias; return e; }

static void gemm_launch(const float* A, const uint8_t* Bp, float* C, int M, int N, int K,
                        int lda, int kcTotal, int S, EpiP ep) {
    dim3 grid((N + 127) / 128, M / 128, S);
    gemm_pk<<<grid, 256, PK_SMEM>>>(A, Bp, C, M, N, K, lda, kcTotal, ep);
}

extern "C" void kernel_launch(void* const* d_in, const int* in_sizes, int n_in,
                              void* d_out, int out_size) {
    const float* enc     = (const float*)d_in[0];
    const float* emb     = (const float*)d_in[1];
    const float* Wfa     = (const float*)d_in[2];
    const float* bfa     = (const float*)d_in[3];
    const float* Wha     = (const float*)d_in[4];
    const float* bha     = (const float*)d_in[5];
    const float* Wv      = (const float*)d_in[6];
    // d_in[7] = bv (cancels in softmax)
    const float* Wh0     = (const float*)d_in[8];
    const float* bh0     = (const float*)d_in[9];
    const float* Wc0     = (const float*)d_in[10];
    const float* bc0     = (const float*)d_in[11];
    const float* gamma_h = (const float*)d_in[12];
    const float* beta_h  = (const float*)d_in[13];
    const float* gamma_c = (const float*)d_in[14];
    const float* beta_c  = (const float*)d_in[15];
    const float* Wfb     = (const float*)d_in[16];
    const float* bfb     = (const float*)d_in[17];
    const float* Wih     = (const float*)d_in[18];
    const float* Whh     = (const float*)d_in[19];
    const float* bih     = (const float*)d_in[20];
    const float* bhh     = (const float*)d_in[21];
    const float* Wfc     = (const float*)d_in[22];
    const float* bfc     = (const float*)d_in[23];
    const int*   caps    = (const int*)d_in[24];
    const int*   lens    = (const int*)d_in[25];

    float* out_pred  = (float*)d_out;
    float* out_alpha = out_pred + (size_t)B * T * V;

    cudaFuncSetAttribute(gemm_pk, cudaFuncAttributeMaxDynamicSharedMemorySize, PK_SMEM);

    float *p_feat, *p_fa, *p_h, *p_c, *p_hW, *p_e, *p_gp, *p_gH, *p_xgc,
          *p_bb, *p_es, *p_eW, *p_part;
    __half* p_ench;
    uint8_t *pk_wcat4, *pk_wihF, *pk_wihE, *pk_wfa, *pk_whc0;
    cudaGetSymbolAddress((void**)&p_feat, g_feat);
    cudaGetSymbolAddress((void**)&p_fa,   g_feat_att);
    cudaGetSymbolAddress((void**)&p_h,    g_hbuf);
    cudaGetSymbolAddress((void**)&p_c,    g_c);
    cudaGetSymbolAddress((void**)&p_hW,   g_hWha);
    cudaGetSymbolAddress((void**)&p_e,    g_e);
    cudaGetSymbolAddress((void**)&p_gp,   g_gatepre);
    cudaGetSymbolAddress((void**)&p_gH,   g_gatesH);
    cudaGetSymbolAddress((void**)&p_xgc,  g_xgc);
    cudaGetSymbolAddress((void**)&p_bb,   g_bihh);
    cudaGetSymbolAddress((void**)&p_es,   g_embseq);
    cudaGetSymbolAddress((void**)&p_eW,   g_embW);
    cudaGetSymbolAddress((void**)&p_part, g_part);
    cudaGetSymbolAddress((void**)&p_ench, g_ench);
    cudaGetSymbolAddress((void**)&pk_wcat4, g_pk_wcat4);
    cudaGetSymbolAddress((void**)&pk_wihF, g_pk_wihF);
    cudaGetSymbolAddress((void**)&pk_wihE, g_pk_wihE);
    cudaGetSymbolAddress((void**)&pk_wfa, g_pk_wfa);
    cudaGetSymbolAddress((void**)&pk_whc0, g_pk_whc0);

    // ---- precompute ----
    enc2h_kernel<<<dim3((int)(((size_t)B * P * F) / 2048)), 256>>>(enc, p_ench);
    pack_kernel<<<dim3(4, 32), 256>>>(Wfa, pk_wfa, NF, F);
    pack_kernel<<<dim3(4, 32), 256>>>(Wh0, pk_whc0, H, F);
    pack_kernel<<<dim3(4, 32), 256>>>(Wc0, pk_whc0 + (size_t)4 * 32 * 32768, H, F);
    pack_kernel<<<dim3(16, 8), 256>>>(Wih, pk_wihE, 4 * H, E + F);
    pack_kernel<<<dim3(16, 32), 256>>>(Wih + E, pk_wihF, 4 * H, E + F);
    pack_kernel<<<dim3(4, 8), 256>>>(Wha, pk_wcat4, 512, H);
    pack_kernel<<<dim3(16, 8), 256>>>(Wfb, pk_wcat4 + (size_t)4 * 8 * 32768, 2048, H);
    pack_kernel<<<dim3(16, 8), 256>>>(Whh, pk_wcat4 + (size_t)20 * 8 * 32768, 2048, H);
    pack_kernel<<<dim3(79, 8), 256>>>(Wfc, pk_wcat4 + (size_t)36 * 8 * 32768, V, H);

    mean_kernel<<<dim3(F / 256, B), 256>>>(enc, p_feat);
    bihh_kernel<<<dim3(4 * H / 256), 256>>>(bih, bhh, p_bb);
    embgather_kernel<<<dim3(E / 256, T * B), 256>>>(emb, caps, p_es);

    // h0 & c0 fused: feat @ [Wh0|Wc0]^T (N=1024, K=2048, S=4 partials)
    gemm_launch(p_feat, pk_whc0, p_part, B, 1024, F, F, 32, 4, ep_partial());
    epi_hc2_kernel<<<dim3(4, B), 256>>>(p_part, bh0, bc0, gamma_h, beta_h, gamma_c, beta_c,
                                        p_h, p_c);

    // embW = embseq(2432x512) @ Wih[:, :E]^T
    gemm_launch(p_es, pk_wihE, p_eW, T * B, 4 * H, E, E, 8, 1, ep_bias(nullptr));

    // feat_att = enc(25088x2048) @ Wfa^T + bfa
    gemm_launch(enc, pk_wfa, p_fa, B * P, NF, F, F, 32, 1, ep_bias(bfa));

    // initial h-side projections from h0 (N=4608: no preds columns; mode 2, S=1)
    {
        EpiP ep = {}; ep.mode = 2;
        ep.bha = bha; ep.bfb = bfb; ep.bihh = p_bb; ep.bfc = bfc;
        ep.lens = lens; ep.t = -1;
        ep.hWha = p_hW; ep.gatepre = p_gp; ep.gatesH = p_gH; ep.out_pred = out_pred;
        gemm_launch(p_h, pk_wcat4, nullptr, B, 4608, H, H, 8, 1, ep);
    }

    // ---- timestep loop: 5 launches per step ----
    for (int t = 0; t < T; t++) {
        att_e_kernel<<<dim3(B * P / 8), 256>>>(p_fa, p_hW, Wv, p_e);
        ctx_gate_kernel<<<dim3(F / 512, B), 256>>>(p_ench, p_e, p_gp, p_xgc,
                                                   out_alpha, lens, t);

        // xgc @ Wih[:, E:]^T  (N=2048, K=2048, S=8 -> 128 CTAs)
        gemm_launch(p_xgc, pk_wihF, p_part, B, 4 * H, F, F, 32, 8, ep_partial());
        lstm_epi_kernel<<<dim3(B * H / 256), 256>>>(p_part, p_gH, p_eW, p_c, p_h, t);

        // combo: h_{t+1} @ [Wha|Wfb|Whh|Wfc]^T -> next-step projections + masked preds(t)
        // mode-2 scatter => S=1 ONLY (one wave: 115 CTAs)
        EpiP ep = {}; ep.mode = 2;
        ep.bha = bha; ep.bfb = bfb; ep.bihh = p_bb; ep.bfc = bfc;
        ep.lens = lens; ep.t = t;
        ep.hWha = p_hW; ep.gatepre = p_gp; ep.gatesH = p_gH; ep.out_pred = out_pred;
        gemm_launch(p_h, pk_wcat4, nullptr, B, NCOMBO, H, H, 8, 1, ep);
    }
}